// round 4
// baseline (speedup 1.0000x reference)
#include <cuda_runtime.h>
#include <cuda_bf16.h>
#include <math_constants.h>
#include <cstdint>

// KCRouteEncoder, fully fused:
//   out = pooled_cid + bias + (pooled_content @ W)    (softmax alphas sum to 1)
// K0: proj_w fp32 -> bf16 (tiny)
// K1: per block of 32 positions: gather+pool into smem (bf16), then
//     block-local bf16 tensor-core GEMM with W streamed from L2 (cp.async,
//     double-buffered, first two chunks prefetched before the gather).

#define KLEV   8
#define EMB    256
#define PDIM   768
#define MAXPOS 12800

#define BM        32
#define BK        32
#define NCHUNK    (PDIM / BK)            // 24
#define P_STRIDE  776                    // bf16 elems per P row (768 + 8 pad)
#define P_ROW_B   (P_STRIDE * 2)         // 1552 bytes
#define P_BYTES   (BM * P_ROW_B)         // 49664
#define W_STRIDE  264                    // bf16 elems per W smem row (256 + 8)
#define W_ROW_B   (W_STRIDE * 2)         // 528
#define W_BUF_B   (BK * W_ROW_B)         // 16896
#define SMEM_TOTAL (P_BYTES + 2 * W_BUF_B)   // 83456

__device__ __nv_bfloat16 g_W[(size_t)PDIM * EMB];

__device__ __forceinline__ uint32_t smem_u32(const void* p) {
    return (uint32_t)__cvta_generic_to_shared(p);
}
__device__ __forceinline__ void cp_async16(uint32_t dst, const void* src) {
    asm volatile("cp.async.cg.shared.global [%0], [%1], 16;\n" :: "r"(dst), "l"(src));
}
__device__ __forceinline__ void cp_commit() {
    asm volatile("cp.async.commit_group;\n");
}
template <int N>
__device__ __forceinline__ void cp_wait() {
    asm volatile("cp.async.wait_group %0;\n" :: "n"(N));
}

// ---------------------------------------------------------------- K0
__global__ void __launch_bounds__(256)
convert_w_kernel(const float* __restrict__ proj_w) {
    int i = blockIdx.x * 256 + threadIdx.x;        // float4 group id
    float4 v = __ldg(((const float4*)proj_w) + i);
    __nv_bfloat162 lo = __floats2bfloat162_rn(v.x, v.y);
    __nv_bfloat162 hi = __floats2bfloat162_rn(v.z, v.w);
    uint2 pk;
    pk.x = *reinterpret_cast<uint32_t*>(&lo);
    pk.y = *reinterpret_cast<uint32_t*>(&hi);
    *reinterpret_cast<uint2*>(g_W + (size_t)i * 4) = pk;
}

// ---------------------------------------------------------------- K1
__global__ void __launch_bounds__(256)
fused_kernel(const int* __restrict__ croutes,
             const float* __restrict__ cid_emb,
             const float* __restrict__ weight,
             const float* __restrict__ content_table,
             const float* __restrict__ proj_b,
             float* __restrict__ out,
             int npos)
{
    extern __shared__ __align__(16) char smem[];
    char* Ps    = smem;                  // [BM][P_STRIDE] bf16
    char* Wbase = smem + P_BYTES;        // [2][BK][W_STRIDE] bf16

    __shared__ int   rels[BM * KLEV];
    __shared__ float alph[BM * KLEV];

    const int t        = threadIdx.x;
    const int warp     = t >> 5;
    const int lane     = t & 31;
    const int blockRow = blockIdx.x * BM;

    // ---- prefetch W chunks 0,1 (land during the gather) ----
    auto load_w_chunk = [&](int kc, int buf) {
        char* Wb = Wbase + buf * W_BUF_B;
#pragma unroll
        for (int i = 0; i < 4; i++) {
            int u  = t + i * 256;          // 0..1023
            int wr = u >> 5, wc = u & 31;  // row 0..31, 16B col 0..31
            cp_async16(smem_u32(Wb + wr * W_ROW_B + wc * 16),
                       g_W + (size_t)(kc * BK + wr) * EMB + wc * 8);
        }
        cp_commit();
    };
    load_w_chunk(0, 0);
    load_w_chunk(1, 1);

    // ---- route ids ----
    {
        int p   = t >> 3;
        int pos = blockRow + p;
        if (pos >= npos) pos = npos - 1;
        rels[t] = croutes[(size_t)pos * KLEV + (t & 7)] + 2;   // 0..NUM_C+1
    }
    __syncthreads();

    // ---- masked softmax, one thread per position ----
    if (t < BM) {
        float nw[KLEV];
        float m = -CUDART_INF_F;
#pragma unroll
        for (int k = 0; k < KLEV; k++) {
            nw[k] = (rels[t * KLEV + k] != 0) ? __ldg(&weight[k]) : -CUDART_INF_F;
            m = fmaxf(m, nw[k]);
        }
        float s = 0.f, ex[KLEV];
#pragma unroll
        for (int k = 0; k < KLEV; k++) { ex[k] = expf(nw[k] - m); s += ex[k]; }
        float inv = 1.f / s;
#pragma unroll
        for (int k = 0; k < KLEV; k++) alph[t * KLEV + k] = ex[k] * inv;
    }
    __syncthreads();

    // ---- gather: 8 threads per position ----
    const int tpos = t >> 3;             // 0..31
    const int sub  = t & 7;              // 0..7
    float a[KLEV]; int r[KLEV];
#pragma unroll
    for (int k = 0; k < KLEV; k++) {
        a[k] = alph[tpos * KLEV + k];
        r[k] = rels[tpos * KLEV + k];
    }

    // content: rows always valid (padding alphas are exactly 0) -> no branches
    const float4* crow[KLEV];
    float         ca[KLEV];
    const float4* drow[KLEV];
    float         da[KLEV];
#pragma unroll
    for (int k = 0; k < KLEV; k++) {
        crow[k] = ((const float4*)content_table) + (size_t)r[k] * 192;
        ca[k]   = a[k];
        int ridx = r[k] - 2;
        da[k]   = (ridx >= 0) ? a[k] : 0.f;
        if (ridx < 0) ridx = 0;
        drow[k] = ((const float4*)cid_emb) + (size_t)ridx * 64;
    }

    char* Prow = Ps + tpos * P_ROW_B;
#pragma unroll 2
    for (int i = 0; i < 24; i++) {
        int c4 = sub + 8 * i;            // float4 column 0..191
        float4 s = make_float4(0.f, 0.f, 0.f, 0.f);
#pragma unroll
        for (int k = 0; k < KLEV; k++) {
            float4 v = __ldg(crow[k] + c4);
            s.x = fmaf(ca[k], v.x, s.x);
            s.y = fmaf(ca[k], v.y, s.y);
            s.z = fmaf(ca[k], v.z, s.z);
            s.w = fmaf(ca[k], v.w, s.w);
        }
        __nv_bfloat162 lo = __floats2bfloat162_rn(s.x, s.y);
        __nv_bfloat162 hi = __floats2bfloat162_rn(s.z, s.w);
        uint2 pk;
        pk.x = *reinterpret_cast<uint32_t*>(&lo);
        pk.y = *reinterpret_cast<uint32_t*>(&hi);
        *reinterpret_cast<uint2*>(Prow + c4 * 8) = pk;
    }

    // cid + bias -> out (fp32 exact); epilogue will RMW-accumulate
    {
        int pos = blockRow + tpos;
        if (pos >= npos) pos = npos - 1;
#pragma unroll
        for (int i = 0; i < 8; i++) {
            int c4 = sub + 8 * i;        // float4 column 0..63
            float4 s = __ldg(((const float4*)proj_b) + c4);
#pragma unroll
            for (int k = 0; k < KLEV; k++) {
                float4 v = __ldg(drow[k] + c4);
                s.x = fmaf(da[k], v.x, s.x);
                s.y = fmaf(da[k], v.y, s.y);
                s.z = fmaf(da[k], v.z, s.z);
                s.w = fmaf(da[k], v.w, s.w);
            }
            *reinterpret_cast<float4*>(out + (size_t)pos * EMB + 4 * c4) = s;
        }
    }
    __syncthreads();

    // ---- block-local GEMM: out[32 rows] += P @ W ----
    float c[2][4][4];
#pragma unroll
    for (int mf = 0; mf < 2; mf++)
#pragma unroll
        for (int nf = 0; nf < 4; nf++)
#pragma unroll
            for (int i = 0; i < 4; i++) c[mf][nf][i] = 0.f;

    for (int kc = 0; kc < NCHUNK; kc++) {
        if (kc < NCHUNK - 1) cp_wait<1>(); else cp_wait<0>();
        __syncthreads();

        const char* Ws = Wbase + (kc & 1) * W_BUF_B;

#pragma unroll
        for (int ks = 0; ks < BK / 16; ks++) {
            uint32_t af[2][4];
#pragma unroll
            for (int mf = 0; mf < 2; mf++) {
                uint32_t addr = smem_u32(Ps + (mf * 16 + (lane & 15)) * P_ROW_B
                                            + kc * 64 + ks * 32 + (lane >> 4) * 16);
                asm volatile("ldmatrix.sync.aligned.m8n8.x4.shared.b16 {%0,%1,%2,%3}, [%4];\n"
                             : "=r"(af[mf][0]), "=r"(af[mf][1]),
                               "=r"(af[mf][2]), "=r"(af[mf][3])
                             : "r"(addr));
            }
            uint32_t bf[4][2];
#pragma unroll
            for (int nf = 0; nf < 4; nf++) {
                int n0 = warp * 32 + nf * 8;
                uint32_t addr = smem_u32(Ws + (ks * 16 + (lane & 15)) * W_ROW_B + n0 * 2);
                asm volatile("ldmatrix.sync.aligned.m8n8.x2.trans.shared.b16 {%0,%1}, [%2];\n"
                             : "=r"(bf[nf][0]), "=r"(bf[nf][1]) : "r"(addr));
            }
#pragma unroll
            for (int mf = 0; mf < 2; mf++)
#pragma unroll
                for (int nf = 0; nf < 4; nf++) {
                    asm volatile(
                        "mma.sync.aligned.m16n8k16.row.col.f32.bf16.bf16.f32 "
                        "{%0,%1,%2,%3}, {%4,%5,%6,%7}, {%8,%9}, {%0,%1,%2,%3};\n"
                        : "+f"(c[mf][nf][0]), "+f"(c[mf][nf][1]),
                          "+f"(c[mf][nf][2]), "+f"(c[mf][nf][3])
                        : "r"(af[mf][0]), "r"(af[mf][1]), "r"(af[mf][2]), "r"(af[mf][3]),
                          "r"(bf[nf][0]), "r"(bf[nf][1]));
                }
        }
        __syncthreads();

        if (kc + 2 < NCHUNK) load_w_chunk(kc + 2, kc & 1);
    }

    // ---- epilogue: out += C ----
#pragma unroll
    for (int mf = 0; mf < 2; mf++) {
#pragma unroll
        for (int nf = 0; nf < 4; nf++) {
            int col  = warp * 32 + nf * 8 + (lane & 3) * 2;
            int row0 = blockRow + mf * 16 + (lane >> 2);
            if (row0 < npos) {
                float2* o = reinterpret_cast<float2*>(&out[(size_t)row0 * EMB + col]);
                float2 v = *o;
                v.x += c[mf][nf][0]; v.y += c[mf][nf][1];
                *o = v;
            }
            int row1 = row0 + 8;
            if (row1 < npos) {
                float2* o = reinterpret_cast<float2*>(&out[(size_t)row1 * EMB + col]);
                float2 v = *o;
                v.x += c[mf][nf][2]; v.y += c[mf][nf][3];
                *o = v;
            }
        }
    }
}

// ---------------------------------------------------------------- launch
extern "C" void kernel_launch(void* const* d_in, const int* in_sizes, int n_in,
                              void* d_out, int out_size)
{
    const int*   croutes       = (const int*)d_in[0];
    // d_in[1] = tailcs (unused)
    const float* cid_emb       = (const float*)d_in[2];
    const float* weight        = (const float*)d_in[3];
    const float* content_table = (const float*)d_in[4];
    const float* proj_w        = (const float*)d_in[5];
    const float* proj_b        = (const float*)d_in[6];
    float*       out           = (float*)d_out;

    int npos = in_sizes[0] / KLEV;
    if (npos > MAXPOS) npos = MAXPOS;

    convert_w_kernel<<<PDIM * EMB / 1024, 256>>>(proj_w);

    static bool attr_set = false;
    if (!attr_set) {
        cudaFuncSetAttribute(fused_kernel,
                             cudaFuncAttributeMaxDynamicSharedMemorySize,
                             SMEM_TOTAL);
        attr_set = true;
    }
    fused_kernel<<<(npos + BM - 1) / BM, 256, SMEM_TOTAL>>>(
        croutes, cid_emb, weight, content_table, proj_b, out, npos);
}

// round 5
// speedup vs baseline: 1.3999x; 1.3999x over previous
#include <cuda_runtime.h>
#include <cuda_bf16.h>
#include <math_constants.h>
#include <cstdint>

// KCRouteEncoder:
//   out = pooled_cid + bias + (pooled_content @ W)     (alphas sum to 1)
// K1 pool (R3, unchanged): float4 gathers, bf16 pooled-content scratch,
//     W fp32->bf16 folded into first 768 blocks.
// K2 gemm v3: BM=32 x BN=256 x BK=32, 3-stage cp.async pipeline, 3 CTAs/SM.

#define KLEV   8
#define EMB    256
#define PDIM   768
#define MAXPOS 12800

#define BM     32
#define BK     32
#define NCHUNK (PDIM / BK)                 // 24
#define NSTAGE 3
#define A_STRIDE_B 80                      // bytes per A smem row (64 + 16 pad)
#define A_STG_B (BM * A_STRIDE_B)          // 2560
#define W_STRIDE_B 528                     // bytes per W smem row (512 + 16 pad)
#define W_STG_B (BK * W_STRIDE_B)          // 16896
#define SMEM_TOTAL (NSTAGE * (A_STG_B + W_STG_B))   // 58368

#define WCONV_BLOCKS (PDIM * EMB / 256)    // 768

__device__ __nv_bfloat16 g_P[(size_t)MAXPOS * PDIM];
__device__ __nv_bfloat16 g_W[(size_t)PDIM * EMB];

__device__ __forceinline__ uint32_t smem_u32(const void* p) {
    return (uint32_t)__cvta_generic_to_shared(p);
}
__device__ __forceinline__ void cp_async16(uint32_t dst, const void* src) {
    asm volatile("cp.async.cg.shared.global [%0], [%1], 16;\n" :: "r"(dst), "l"(src));
}
__device__ __forceinline__ void cp_commit() {
    asm volatile("cp.async.commit_group;\n");
}
template <int N>
__device__ __forceinline__ void cp_wait() {
    asm volatile("cp.async.wait_group %0;\n" :: "n"(N));
}

// ------------------------------------------------ fallback W convert (npos<768 only)
__global__ void convert_w_kernel(const float* __restrict__ proj_w) {
    int i = blockIdx.x * blockDim.x + threadIdx.x;
    if (i < PDIM * EMB)
        g_W[i] = __float2bfloat16_rn(__ldg(&proj_w[i]));
}

// ------------------------------------------------ K1: pool (identical to R3)
__global__ void __launch_bounds__(256)
pool_kernel(const int* __restrict__ croutes,
            const float* __restrict__ cid_emb,
            const float* __restrict__ weight,
            const float* __restrict__ content_table,
            const float* __restrict__ proj_w,
            const float* __restrict__ proj_b,
            float* __restrict__ out,
            int npos)
{
    const int pos = blockIdx.x;
    const int t   = threadIdx.x;

    if (blockIdx.x < WCONV_BLOCKS) {
        int i = blockIdx.x * 256 + t;
        g_W[i] = __float2bfloat16_rn(__ldg(&proj_w[i]));
    }
    if (pos >= npos) return;

    __shared__ int   rels[KLEV];
    __shared__ float alph[KLEV];

    if (t < KLEV)
        rels[t] = croutes[(size_t)pos * KLEV + t] + 2;
    __syncthreads();

    if (t == 0) {
        float nw[KLEV];
        float m = -CUDART_INF_F;
#pragma unroll
        for (int k = 0; k < KLEV; k++) {
            nw[k] = (rels[k] != 0) ? __ldg(&weight[k]) : -CUDART_INF_F;
            m = fmaxf(m, nw[k]);
        }
        float s = 0.f, ex[KLEV];
#pragma unroll
        for (int k = 0; k < KLEV; k++) { ex[k] = expf(nw[k] - m); s += ex[k]; }
        float inv = 1.f / s;
#pragma unroll
        for (int k = 0; k < KLEV; k++) alph[k] = ex[k] * inv;
    }
    __syncthreads();

    float a[KLEV]; int r[KLEV];
#pragma unroll
    for (int k = 0; k < KLEV; k++) { a[k] = alph[k]; r[k] = rels[k]; }

    if (t < 192) {
        float4 s = make_float4(0.f, 0.f, 0.f, 0.f);
#pragma unroll
        for (int k = 0; k < KLEV; k++) {
            if (a[k] != 0.f) {
                float4 v = __ldg(((const float4*)content_table) + (size_t)r[k] * 192 + t);
                s.x = fmaf(a[k], v.x, s.x);
                s.y = fmaf(a[k], v.y, s.y);
                s.z = fmaf(a[k], v.z, s.z);
                s.w = fmaf(a[k], v.w, s.w);
            }
        }
        __nv_bfloat162 lo = __floats2bfloat162_rn(s.x, s.y);
        __nv_bfloat162 hi = __floats2bfloat162_rn(s.z, s.w);
        uint2 pk;
        pk.x = *reinterpret_cast<uint32_t*>(&lo);
        pk.y = *reinterpret_cast<uint32_t*>(&hi);
        *reinterpret_cast<uint2*>(g_P + (size_t)pos * PDIM + 4 * t) = pk;
    } else {
        int u = t - 192;
        float4 s = __ldg(((const float4*)proj_b) + u);
#pragma unroll
        for (int k = 0; k < KLEV; k++) {
            if (a[k] != 0.f && r[k] >= 2) {
                float4 v = __ldg(((const float4*)cid_emb) + (size_t)(r[k] - 2) * 64 + u);
                s.x = fmaf(a[k], v.x, s.x);
                s.y = fmaf(a[k], v.y, s.y);
                s.z = fmaf(a[k], v.z, s.z);
                s.w = fmaf(a[k], v.w, s.w);
            }
        }
        *reinterpret_cast<float4*>(out + (size_t)pos * EMB + 4 * u) = s;
    }
}

// ------------------------------------------------ K2: GEMM v3
// out[M,256] += g_P[M,768] @ g_W[768,256]
// BM=32, BK=32, 3-stage pipeline; 8 warps, warp w -> cols [32w, 32w+32)
__global__ void __launch_bounds__(256, 3)
gemm_kernel(float* __restrict__ out, int npos)
{
    extern __shared__ __align__(16) char smem[];
    // layout: [NSTAGE][ A(2560B) then W(16896B) ]
    const int t    = threadIdx.x;
    const int warp = t >> 5;
    const int lane = t & 31;
    const int blockRow = blockIdx.x * BM;

    float c[2][4][4];
#pragma unroll
    for (int mf = 0; mf < 2; mf++)
#pragma unroll
        for (int nf = 0; nf < 4; nf++)
#pragma unroll
            for (int i = 0; i < 4; i++) c[mf][nf][i] = 0.f;

    // A: 32 rows x 32 bf16 = 128 x 16B, threads t<128
    const int a_row = t >> 2, a_c16 = t & 3;
    int gr = blockRow + a_row; if (gr >= npos) gr = npos - 1;
    const __nv_bfloat16* a_src = g_P + (size_t)gr * PDIM + a_c16 * 8;

    auto load_chunk = [&](int kc, int stg) {
        char* base = smem + stg * (A_STG_B + W_STG_B);
        if (t < 128)
            cp_async16(smem_u32(base + a_row * A_STRIDE_B + a_c16 * 16),
                       a_src + kc * BK);
        char* Wb = base + A_STG_B;
#pragma unroll
        for (int i = 0; i < 4; i++) {
            int u  = t + i * 256;            // 0..1023
            int wr = u >> 5, wc = u & 31;    // row 0..31, 16B col 0..31
            cp_async16(smem_u32(Wb + wr * W_STRIDE_B + wc * 16),
                       g_W + (size_t)(kc * BK + wr) * EMB + wc * 8);
        }
        cp_commit();
    };

    load_chunk(0, 0);
    load_chunk(1, 1);
    load_chunk(2, 2);

    int stg = 0;
    for (int kc = 0; kc < NCHUNK; kc++) {
        if (kc + 2 < NCHUNK)      cp_wait<2>();
        else if (kc + 1 < NCHUNK) cp_wait<1>();
        else                      cp_wait<0>();
        __syncthreads();

        const char* base = smem + stg * (A_STG_B + W_STG_B);
        const char* As = base;
        const char* Ws = base + A_STG_B;

#pragma unroll
        for (int ks = 0; ks < BK / 16; ks++) {
            uint32_t af[2][4];
#pragma unroll
            for (int mf = 0; mf < 2; mf++) {
                uint32_t addr = smem_u32(As + (mf * 16 + (lane & 15)) * A_STRIDE_B
                                            + ks * 32 + (lane >> 4) * 16);
                asm volatile("ldmatrix.sync.aligned.m8n8.x4.shared.b16 {%0,%1,%2,%3}, [%4];\n"
                             : "=r"(af[mf][0]), "=r"(af[mf][1]),
                               "=r"(af[mf][2]), "=r"(af[mf][3])
                             : "r"(addr));
            }
            uint32_t bf[4][2];
#pragma unroll
            for (int nf = 0; nf < 4; nf++) {
                int n0 = warp * 32 + nf * 8;
                uint32_t addr = smem_u32(Ws + (ks * 16 + (lane & 15)) * W_STRIDE_B + n0 * 2);
                asm volatile("ldmatrix.sync.aligned.m8n8.x2.trans.shared.b16 {%0,%1}, [%2];\n"
                             : "=r"(bf[nf][0]), "=r"(bf[nf][1]) : "r"(addr));
            }
#pragma unroll
            for (int mf = 0; mf < 2; mf++)
#pragma unroll
                for (int nf = 0; nf < 4; nf++) {
                    asm volatile(
                        "mma.sync.aligned.m16n8k16.row.col.f32.bf16.bf16.f32 "
                        "{%0,%1,%2,%3}, {%4,%5,%6,%7}, {%8,%9}, {%0,%1,%2,%3};\n"
                        : "+f"(c[mf][nf][0]), "+f"(c[mf][nf][1]),
                          "+f"(c[mf][nf][2]), "+f"(c[mf][nf][3])
                        : "r"(af[mf][0]), "r"(af[mf][1]), "r"(af[mf][2]), "r"(af[mf][3]),
                          "r"(bf[nf][0]), "r"(bf[nf][1]));
                }
        }
        __syncthreads();

        if (kc + NSTAGE < NCHUNK) load_chunk(kc + NSTAGE, stg);
        stg = (stg == NSTAGE - 1) ? 0 : stg + 1;
    }

    // epilogue: out += C
#pragma unroll
    for (int mf = 0; mf < 2; mf++) {
#pragma unroll
        for (int nf = 0; nf < 4; nf++) {
            int col  = warp * 32 + nf * 8 + (lane & 3) * 2;
            int row0 = blockRow + mf * 16 + (lane >> 2);
            if (row0 < npos) {
                float2* o = reinterpret_cast<float2*>(&out[(size_t)row0 * EMB + col]);
                float2 v = *o;
                v.x += c[mf][nf][0]; v.y += c[mf][nf][1];
                *o = v;
            }
            int row1 = row0 + 8;
            if (row1 < npos) {
                float2* o = reinterpret_cast<float2*>(&out[(size_t)row1 * EMB + col]);
                float2 v = *o;
                v.x += c[mf][nf][2]; v.y += c[mf][nf][3];
                *o = v;
            }
        }
    }
}

// ------------------------------------------------ launch
extern "C" void kernel_launch(void* const* d_in, const int* in_sizes, int n_in,
                              void* d_out, int out_size)
{
    const int*   croutes       = (const int*)d_in[0];
    // d_in[1] = tailcs (unused)
    const float* cid_emb       = (const float*)d_in[2];
    const float* weight        = (const float*)d_in[3];
    const float* content_table = (const float*)d_in[4];
    const float* proj_w        = (const float*)d_in[5];
    const float* proj_b        = (const float*)d_in[6];
    float*       out           = (float*)d_out;

    int npos = in_sizes[0] / KLEV;
    if (npos > MAXPOS) npos = MAXPOS;

    if (npos < WCONV_BLOCKS)
        convert_w_kernel<<<(PDIM * EMB + 255) / 256, 256>>>(proj_w);

    pool_kernel<<<npos, 256>>>(croutes, cid_emb, weight, content_table,
                               proj_w, proj_b, out, npos);

    static bool attr_set = false;
    if (!attr_set) {
        cudaFuncSetAttribute(gemm_kernel,
                             cudaFuncAttributeMaxDynamicSharedMemorySize,
                             SMEM_TOTAL);
        attr_set = true;
    }
    gemm_kernel<<<(npos + BM - 1) / BM, 256, SMEM_TOTAL>>>(out, npos);
}